// round 17
// baseline (speedup 1.0000x reference)
#include <cuda_runtime.h>

#define BATCH   4096
#define IN_W    1024
#define DEPTH   8
#define BLOCKS  64
#define NACT    8
#define GROW    512
#define TOTAL   5120
#define OUT_W   512

// 84 MB scratch (static; only ~peak-live slots are ever touched -> L2-resident)
__device__ float g_data[(size_t)TOTAL * BATCH];

typedef unsigned long long ull;

// Slot plan (computed once per launch by plan_kernel):
//   g_slot_gather[m][i] : slot of row indices[m][i]   (gather & scatter addr)
//   g_slot_act[m][u]    : slot for act row IN_W+512m+u, or -1 if never read
//   g_alive[m][i]       : row indices[m][i] is read again after module m
__device__ int           g_slot_gather[DEPTH][1024];
__device__ int           g_slot_act[DEPTH - 1][512];
__device__ unsigned char g_alive[DEPTH][1024];

__device__ __forceinline__ ull pk2(float x, float y) {
    ull r; asm("mov.b64 %0, {%1, %2};" : "=l"(r) : "f"(x), "f"(y)); return r;
}
__device__ __forceinline__ void upk2(ull v, float& x, float& y) {
    asm("mov.b64 {%0, %1}, %2;" : "=f"(x), "=f"(y) : "l"(v));
}
// Packed f32x2 FMA/MUL — Blackwell FFMA2 path (PTX-only)
__device__ __forceinline__ ull fma2(ull a, ull b, ull c) {
    ull d; asm("fma.rn.f32x2 %0, %1, %2, %3;" : "=l"(d) : "l"(a), "l"(b), "l"(c)); return d;
}
__device__ __forceinline__ ull mul2(ull a, ull b) {
    ull d; asm("mul.rn.f32x2 %0, %1, %2;" : "=l"(d) : "l"(a), "l"(b)); return d;
}
__device__ __forceinline__ float sqrt_ap(float x) {
    float r; asm("sqrt.approx.f32 %0, %1;" : "=f"(r) : "f"(x)); return r;
}
__device__ __forceinline__ float actf(float p) {
    return 0.5f * (p + sqrt_ap(fmaf(p, p, 1.0f)));
}
__device__ __forceinline__ ull mk_keep() {     // evict_last: re-read later
    ull pol;
    asm("createpolicy.fractional.L2::evict_last.b64 %0, 1.0;" : "=l"(pol));
    return pol;
}
__device__ __forceinline__ ull mk_stream() {   // evict_first: last use
    ull pol;
    asm("createpolicy.fractional.L2::evict_first.b64 %0, 1.0;" : "=l"(pol));
    return pol;
}
__device__ __forceinline__ ull ldg_pol(const float* p, ull pol) {
    ull v;
    asm volatile("ld.global.L2::cache_hint.b64 %0, [%1], %2;"
                 : "=l"(v) : "l"(p), "l"(pol));
    return v;
}
__device__ __forceinline__ void stg_pol(float* p, ull v, ull pol) {
    asm volatile("st.global.L2::cache_hint.b64 [%0], %1, %2;"
                 :: "l"(p), "l"(v), "l"(pol));
}
__device__ __forceinline__ void stg_cs(float* p, ull v) {
    asm volatile("st.global.cs.b64 [%0], %1;" :: "l"(p), "l"(v));
}

// ---------------------------------------------------------------------------
// Exclusive rank among flag==1 threads (1024-thread CTA) + total.
// ballot/popc within warps, shuffle-scan over the 32 warp totals.
// ---------------------------------------------------------------------------
__device__ __forceinline__ int rank_scan(int flag, int t,
                                         int* warptot, int* s_total) {
    unsigned mask = __ballot_sync(0xffffffffu, flag != 0);
    int lane = t & 31, w = t >> 5;
    int wrank = __popc(mask & ((1u << lane) - 1u));
    if (lane == 0) warptot[w] = __popc(mask);
    __syncthreads();
    if (t < 32) {
        int orig = warptot[t];
        int v = orig;
        #pragma unroll
        for (int off = 1; off < 32; off <<= 1) {
            int n = __shfl_up_sync(0xffffffffu, v, off);
            if (lane >= off) v += n;
        }
        warptot[t] = v - orig;              // exclusive warp offset
        if (t == 31) *s_total = v;          // grand total
    }
    __syncthreads();
    return warptot[w] + wrank;
}

// ---------------------------------------------------------------------------
// One-time slot planner (single 1024-thread CTA).
// Rows get slots; slots freed one module AFTER the row's last read (so a
// freed slot is never concurrently gathered and act-written in one module),
// then reused LIFO. Fresh slots only when the stack is empty -> touched
// address range == peak live rows (~40 MB) -> state stays L2-resident.
// ---------------------------------------------------------------------------
__global__ void plan_kernel(const int* __restrict__ idxs) {
    __shared__ signed char last_read[TOTAL];   // last module reading row r
    __shared__ short       slot_of[TOTAL];
    __shared__ short       stack[TOTAL];
    __shared__ int warptot[32];
    __shared__ int s_total, s_top, s_fresh;
    const int t = threadIdx.x;

    for (int i = t; i < TOTAL; i += 1024) last_read[i] = -1;
    __syncthreads();
    for (int m = 0; m < DEPTH; m++) {          // ascending: final = last read
        last_read[idxs[m * 1024 + t]] = (signed char)m;
        __syncthreads();
    }
    slot_of[t] = (short)t;                     // input rows: identity slots
    if (t == 0) { s_top = 0; s_fresh = 1024; }
    __syncthreads();

    for (int m = 0; m < DEPTH; m++) {
        // 1) Free slots of rows whose last read was module m-1.
        if (m > 0) {
            int r    = idxs[(m - 1) * 1024 + t];
            int dead = (last_read[r] == (signed char)(m - 1));
            int rk   = rank_scan(dead, t, warptot, &s_total);
            int top  = s_top;
            if (dead) stack[top + rk] = slot_of[r];
            __syncthreads();
            if (t == 0) s_top = top + s_total;
            __syncthreads();
        }
        // 2) Record gather slots + alive mask for module m.
        {
            int r = idxs[m * 1024 + t];
            g_slot_gather[m][t] = (int)slot_of[r];
            g_alive[m][t] = (unsigned char)(last_read[r] > (signed char)m);
        }
        // 3) Allocate slots for module m's live act rows (m < 7).
        if (m < DEPTH - 1) {
            int alive = 0, row = 0;
            if (t < 512) {
                row = IN_W + GROW * m + t;
                alive = (last_read[row] >= 0);
            }
            int rk   = rank_scan(alive, t, warptot, &s_total);
            int top  = s_top, fresh = s_fresh;
            if (t < 512) {
                if (alive) {
                    int slot = (rk < top) ? (int)stack[top - 1 - rk]
                                          : (fresh + rk - top);
                    slot_of[row]    = (short)slot;
                    g_slot_act[m][t] = slot;
                } else {
                    g_slot_act[m][t] = -1;
                }
            }
            __syncthreads();
            if (t == 0) {
                int K = s_total;
                int used = (K < top) ? K : top;
                s_top   = top - used;
                s_fresh = fresh + (K - used);
            }
            __syncthreads();
        }
    }
}

// ---------------------------------------------------------------------------
// One butterfly module. CUDA block = (butterfly blk) x (256 batch cols).
// Thread owns 2 batch columns of all 16 rows as f32x2; transform in registers.
// occ-7 cap (72 regs) -> all 1024 CTAs in ONE wave, 28 warps/SM.
// g_data is addressed by SLOT (compacted, L2-resident working set).
// PDL prologue computes trig via sincosf; predecessor-produced data only
// touched after griddepsync (module 0's slot tables come from plan_kernel,
// its immediate predecessor -> staged post-sync after the IN rotations).
// MODE: 0 = middle, 1 = first (input*scales), 2 = last (act -> d_out)
// ---------------------------------------------------------------------------
template<int MODE>
__global__ __launch_bounds__(128, 7)
void module_kernel(const float* __restrict__ biases,  // [512]    this module
                   const int*   __restrict__ idx,     // [1024]   this module
                   const float* __restrict__ angles,  // [8][512] this module
                   int mod,
                   const float* __restrict__ input,   // (1024,4096) for FIRST
                   const float* __restrict__ scales,  // (1024,)     for FIRST
                   float* __restrict__ out_ext)       // d_out for LAST
{
    const int blk = blockIdx.y;
    const int tid = threadIdx.x;

    __shared__ int   s_slot[16];
    __shared__ int   s_actslot[NACT];
    __shared__ int   s_idx[16];
    __shared__ ull   s_scl[16];
    __shared__ float s_bias[NACT];
    __shared__ unsigned char s_alsc[16];
    __shared__ __align__(16) ulonglong2 s_cs[64];

    // ---- PDL prologue: trig + tables that predate the predecessor ----
    if (tid < 64) {
        int L = tid >> 3, a = tid & 7;
        float sn, cs;
        sincosf(angles[L * 512 + blk * 8 + a], &sn, &cs);
        s_cs[tid] = make_ulonglong2(pk2(cs, cs), pk2(sn, sn));
    }
    if (tid < 16) {
        if (MODE == 1) {
            int row = idx[blk * 16 + tid];
            s_idx[tid] = row;
            float s = scales[row];
            s_scl[tid] = pk2(s, s);
        } else {
            // plan_kernel is >= 2 launches back for modules >= 1: safe here.
            s_slot[tid] = g_slot_gather[mod][blk * 16 + tid];
            s_alsc[tid] = g_alive[mod][blk * 16 + tid];
        }
    }
    if (tid < 8) {
        s_bias[tid] = biases[blk * 8 + tid];
        if (MODE == 0) s_actslot[tid] = g_slot_act[mod][blk * NACT + tid];
    }
    __syncthreads();

    const int b = (blockIdx.x * 128 + tid) * 2;   // first of 2 batch cols
    const ull SGN = 0x8000000080000000ULL;
    const ull pk  = mk_keep();
    const ull ps  = mk_stream();

    // ---- wait for previous module's stores (middle/last) ----
    if (MODE != 1) cudaGridDependencySynchronize();

    // Gather 16 rows (16 independent LDG.64 -> MLP=16). Last-use rows get
    // evict_first (their slots are recycled; they are never scattered back).
    ull v[16];
    #pragma unroll
    for (int j = 0; j < 16; j++) {
        if (MODE == 1)
            v[j] = *(const ull*)(input + (size_t)s_idx[j] * BATCH + b);
        else
            v[j] = ldg_pol(g_data + (size_t)s_slot[j] * BATCH + b,
                           s_alsc[j] ? pk : ps);
    }
    if (MODE == 1) {
        #pragma unroll
        for (int j = 0; j < 16; j++) v[j] = mul2(v[j], s_scl[j]);
    }

    // 4 IN rotation layers (strides 1,2,4,8), all in registers
    #pragma unroll
    for (int k = 0; k < 4; k++) {
        const int st = 1 << k;
        #pragma unroll
        for (int g = 0; g < 16; g += 2 * st) {
            #pragma unroll
            for (int j = 0; j < st; j++) {
                const int lo = g + j, hi = lo + st;
                const ulonglong2 cs = s_cs[k * 8 + (g >> 1) + j];  // LDS.128
                const ull ns = cs.y ^ SGN;                         // -s on ALU
                ull xl = v[lo], xh = v[hi];
                v[lo] = fma2(cs.x, xl, mul2(cs.y, xh));
                v[hi] = fma2(ns,   xl, mul2(cs.x, xh));
            }
        }
    }

    // MODE 1: slot tables come from plan_kernel (our PDL predecessor) —
    // stage them now that the overlapped work is done.
    if (MODE == 1) {
        cudaGridDependencySynchronize();
        if (tid < 16) {
            s_slot[tid] = g_slot_gather[0][blk * 16 + tid];
            s_alsc[tid] = g_alive[0][blk * 16 + tid];
        }
        if (tid < 8) s_actslot[tid] = g_slot_act[0][blk * NACT + tid];
        __syncthreads();
    }

    // Activation on rows 0..7; write live act rows (d_out for last module)
    #pragma unroll
    for (int u = 0; u < NACT; u++) {
        const float bb = s_bias[u];
        float x0, x1;
        upk2(v[u], x0, x1);
        x0 = actf(x0 + bb); x1 = actf(x1 + bb);
        v[u] = pk2(x0, x1);
        if (MODE == 2)
            stg_cs(out_ext + (size_t)(blk * NACT + u) * BATCH + b, v[u]);
        else if (s_actslot[u] >= 0)
            stg_pol(g_data + (size_t)s_actslot[u] * BATCH + b, v[u], pk);
    }

    if (MODE != 2) {
        // 4 OUT rotation layers (trig layers 4..7, strides 1,2,4,8)
        #pragma unroll
        for (int k = 0; k < 4; k++) {
            const int st = 1 << k;
            #pragma unroll
            for (int g = 0; g < 16; g += 2 * st) {
                #pragma unroll
                for (int j = 0; j < st; j++) {
                    const int lo = g + j, hi = lo + st;
                    const ulonglong2 cs = s_cs[(4 + k) * 8 + (g >> 1) + j];
                    const ull ns = cs.y ^ SGN;
                    ull xl = v[lo], xh = v[hi];
                    v[lo] = fma2(cs.x, xl, mul2(cs.y, xh));
                    v[hi] = fma2(ns,   xl, mul2(cs.x, xh));
                }
            }
        }
        // Scatter back only live rows, by slot (warp-uniform predicate)
        #pragma unroll
        for (int j = 0; j < 16; j++)
            if (s_alsc[j])
                stg_pol(g_data + (size_t)s_slot[j] * BATCH + b, v[j], pk);
    }

    // Let the next PDL kernel in as soon as our work is done.
    cudaTriggerProgrammaticLaunchCompletion();
}

// ---------------------------------------------------------------------------
extern "C" void kernel_launch(void* const* d_in, const int* in_sizes, int n_in,
                              void* d_out, int out_size) {
    const float* input   = (const float*)d_in[0];   // (1024, 4096)
    const float* scales  = (const float*)d_in[1];   // (1024,)
    const float* angles  = (const float*)d_in[2];   // (8, 8, 512)
    const float* biases  = (const float*)d_in[3];   // (8, 512)
    const int*   indices = (const int*)d_in[4];     // (8, 1024)
    float* out = (float*)d_out;                     // (512, 4096)

    plan_kernel<<<1, 1024>>>(indices);

    dim3 grid(BATCH / (128 * 2), BLOCKS);   // (16, 64) = 1024 CTAs, one wave

    // All modules PDL-launched; module 0 overlaps with plan_kernel,
    // modules 1..7 with the previous module.
    for (int m = 0; m < DEPTH; m++) {
        const float* bia = biases + (size_t)m * 512;
        const int*   ix  = indices + (size_t)m * 1024;
        const float* ang = angles + (size_t)m * 4096;

        cudaLaunchConfig_t cfg = {};
        cfg.gridDim  = grid;
        cfg.blockDim = dim3(128, 1, 1);
        cfg.dynamicSmemBytes = 0;
        cfg.stream = 0;
        cudaLaunchAttribute at[1];
        at[0].id = cudaLaunchAttributeProgrammaticStreamSerialization;
        at[0].val.programmaticStreamSerializationAllowed = 1;
        cfg.attrs = at;
        cfg.numAttrs = 1;

        if (m == 0)
            cudaLaunchKernelEx(&cfg, module_kernel<1>, bia, ix, ang, m,
                               input, scales, (float*)nullptr);
        else if (m < DEPTH - 1)
            cudaLaunchKernelEx(&cfg, module_kernel<0>, bia, ix, ang, m,
                               (const float*)nullptr, (const float*)nullptr,
                               (float*)nullptr);
        else
            cudaLaunchKernelEx(&cfg, module_kernel<2>, bia, ix, ang, m,
                               (const float*)nullptr, (const float*)nullptr,
                               out);
    }
}